// round 13
// baseline (speedup 1.0000x reference)
#include <cuda_runtime.h>
#include <cuda_fp16.h>
#include <math.h>
#include <stdint.h>

// ---------------- problem constants ----------------
#define SEQ   4608
#define HEADS 8
#define HDIM  128
#define NB    36
#define POOL  128
#define FFLN  384
#define KEEP  4
#define PROT  6
#define HBLK  8192    // 128*128 fp16 elements = 8192 u32 per (head, block)

// ---------------- device scratch ----------------
__device__ uint32_t d_kf[HEADS * NB * HBLK];  // K B-frag fp16 (k=dim, n=token)
__device__ uint32_t d_vf[HEADS * NB * HBLK];  // V B-frag fp16 (k=token, n=dim)
__device__ float d_qp[HEADS * NB * HDIM];
__device__ float d_kp[HEADS * NB * HDIM];
__device__ unsigned long long d_maskbits[HEADS * NB];
__device__ float d_po[2 * NB * HEADS * POOL * HDIM];  // partial O (unnormalized)
__device__ float d_pl[2 * NB * HEADS * POOL];          // partial row sums

// qkv2 position j -> original token index (verified round 1)
__device__ __forceinline__ int perm_of(int j) {
    if (j < 3840) {
        int b = j >> 7, w = j & 127;
        int fn = b / 6, hn = (b % 6) / 3, wn = b % 3;
        int f2 = w >> 6, r = (w >> 3) & 7, c = w & 7;
        return FFLN + (fn * 2 + f2) * 384 + (hn * 8 + r) * 24 + (wn * 8 + c);
    } else if (j < 4224) {
        return j - 3840;
    } else {
        return j;
    }
}

__device__ __forceinline__ uint32_t pack_hf2(float lo, float hi) {
    uint32_t r;
    asm("cvt.rn.f16x2.f32 %0, %1, %2;" : "=r"(r) : "f"(hi), "f"(lo));
    return r;
}
__device__ __forceinline__ float ex2f(float x) {
    float y;
    asm("ex2.approx.ftz.f32 %0, %1;" : "=f"(y) : "f"(x));
    return y;
}

// fp16 m16n8k16 B-frag builder: kx = MMA k-index, nx = MMA n-index;
// adjacent 8-wide n-tiles paired into one uint4 slot.
// returns fp16 element index (u32 slot * 2 + half)
__device__ __forceinline__ int idxBhf(int kx, int nx) {
    int kc = kx >> 4, kk = kx & 15;
    int q4 = (kk >> 1) & 3, hk = kk >> 3, half = kk & 1;
    int np = nx >> 4, odd = (nx >> 3) & 1, g = nx & 7;
    int slot = ((kc * 8 + np) * 32 + g * 4 + q4) * 4 + odd * 2 + hk;
    return slot * 2 + half;
}
// fp16 m16n8k16 A-frag (Q/P, 128 rows): r = row (0..127), c = k-index (0..127)
__device__ __forceinline__ int idxAhf(int r, int c) {
    int slot = (((c >> 4) * 8 + (r >> 4)) * 32 + (r & 7) * 4 + ((c >> 1) & 3)) * 4
             + ((r >> 3) & 1) + (((c >> 3) & 1) << 1);
    return slot * 2 + (c & 1);
}

__device__ __forceinline__ void mma_f16(float c[4], const uint32_t a[4], uint32_t b0, uint32_t b1) {
    asm volatile(
        "mma.sync.aligned.m16n8k16.row.col.f32.f16.f16.f32 "
        "{%0,%1,%2,%3}, {%4,%5,%6,%7}, {%8,%9}, {%0,%1,%2,%3};\n"
        : "+f"(c[0]), "+f"(c[1]), "+f"(c[2]), "+f"(c[3])
        : "r"(a[0]), "r"(a[1]), "r"(a[2]), "r"(a[3]), "r"(b0), "r"(b1));
}

__device__ __forceinline__ void cp16(uint32_t s, const void* g) {
    asm volatile("cp.async.cg.shared.global [%0], [%1], 16;" :: "r"(s), "l"(g));
}
#define CP_COMMIT() asm volatile("cp.async.commit_group;")
#define CP_WAIT1()  asm volatile("cp.async.wait_group 1;")

// ---------------- 1) gather/permute K,V + pool q,k ------------------------
// grid (NB, HEADS, 3), 512 threads: z=0 q-pool, z=1 K frags + pool, z=2 V frags.
__global__ void gather_k(const float* __restrict__ q,
                         const float* __restrict__ k,
                         const float* __restrict__ v) {
    extern __shared__ uint32_t stg[];            // HBLK u32
    float* psm = (float*)(stg + HBLK);           // 512
    int* sperm = (int*)(psm + 512);              // 128
    const int bl = blockIdx.x, h = blockIdx.y, z = blockIdx.z;
    const int tid = threadIdx.x;
    const int d = tid & 127, t0 = tid >> 7;      // t0 in 0..3

    if (tid < 128)
        sperm[tid] = perm_of(bl * POOL + tid) * (HEADS * HDIM) + h * HDIM;
    __syncthreads();

    if (z == 0) {
        float part = 0.f;
#pragma unroll 16
        for (int i = 0; i < 32; i++) part += q[(size_t)sperm[t0 + 4 * i] + d];
        psm[tid] = part;
        __syncthreads();
        if (tid < 128)
            d_qp[(size_t)(h * NB + bl) * HDIM + tid] =
                (psm[tid] + psm[tid + 128] + psm[tid + 256] + psm[tid + 384])
                * (1.0f / POOL);
    } else if (z == 1) {
        __half* hstg = (__half*)stg;
        float part = 0.f;
#pragma unroll 16
        for (int i = 0; i < 32; i++) {
            int t = t0 + 4 * i;
            float val = k[(size_t)sperm[t] + d];
            part += val;
            hstg[idxBhf(d, t)] = __float2half(val);   // k-index = dim, n = token
        }
        psm[tid] = part;
        __syncthreads();
        uint4* dst = (uint4*)(d_kf + (size_t)(h * NB + bl) * HBLK);
        const uint4* src = (const uint4*)stg;
#pragma unroll
        for (int i = 0; i < 4; i++) dst[tid + 512 * i] = src[tid + 512 * i];
        if (tid < 128)
            d_kp[(size_t)(h * NB + bl) * HDIM + tid] =
                (psm[tid] + psm[tid + 128] + psm[tid + 256] + psm[tid + 384])
                * (1.0f / POOL);
    } else {
        __half* hstg = (__half*)stg;
#pragma unroll 16
        for (int i = 0; i < 32; i++) {
            int t = t0 + 4 * i;
            hstg[idxBhf(t, d)] = __float2half(v[(size_t)sperm[t] + d]);  // k = token, n = dim
        }
        __syncthreads();
        uint4* dst = (uint4*)(d_vf + (size_t)(h * NB + bl) * HBLK);
        const uint4* src = (const uint4*)stg;
#pragma unroll
        for (int i = 0; i < 4; i++) dst[tid + 512 * i] = src[tid + 512 * i];
    }
}

// ---------------- 2) top-4 threshold -> block mask ------------------------
__global__ void mask_k() {
    int l = blockIdx.x, h = blockIdx.y;
    __shared__ float lg[NB];
    int s = threadIdx.x;
    if (s < NB) {
        const float* qv = d_qp + ((size_t)h * NB + l) * HDIM;
        const float* kv = d_kp + ((size_t)h * NB + s) * HDIM;
        float acc = 0.f;
        for (int t = 0; t < HDIM; t++) acc += qv[t] * kv[t];
        lg[s] = acc;
    }
    __syncthreads();
    if (threadIdx.x == 0) {
        float vals[NB];
        for (int i = 0; i < NB; i++) vals[i] = lg[i];
        float thr = 0.f;
        for (int it = 0; it < KEEP; it++) {
            int bi = 0; float bv = -INFINITY;
            for (int i = 0; i < NB; i++) if (vals[i] > bv) { bv = vals[i]; bi = i; }
            thr = bv; vals[bi] = -INFINITY;
        }
        unsigned long long m = 0;
        for (int i = 0; i < NB; i++) if (lg[i] >= thr) m |= 1ull << i;
        m |= ((1ull << PROT) - 1ull) << (NB - PROT);
        if (l >= NB - PROT) m = (1ull << NB) - 1ull;
        d_maskbits[(size_t)h * NB + l] = m;
    }
}

// ---------------- 3) all-fp16 attention, key-block split-K ----------------
// CTA = (qblock, head, half-of-key-list). 512 threads, 4x4 warp grid, warp
// tile 32x32. Halves process DISJOINT key blocks (no K/V duplication); the
// no-max softmax makes the combine a pure addition (no rescale).
__global__ void __launch_bounds__(512, 1)
attn_k(const float* __restrict__ qsrc) {
    extern __shared__ uint32_t sm[];
    uint32_t* sQ = sm;                         // 8192 (32KB) fp16 A-frags
    uint32_t* sK = sm + 8192;                  // 8192 (32KB) fp16 B-frags
    uint32_t* sV = sm + 16384;                 // 8192 (32KB) fp16 B-frags
    uint32_t* sP = sm + 24576;                 // 8192 (32KB) fp16 A-frags
    float* lsm = (float*)(sm + 32768);         // 128 x 4
    int* sperm = (int*)(lsm + 512);            // 128

    // heavy-first ordering; (qb 30..35) x 2 halves first. Plain subtraction.
    int bx = blockIdx.x;
    int qb, h, half;
    if (bx < 96) {
        half = bx >= 48;
        int u = half ? bx - 48 : bx;           // 0..47
        h = u & 7; qb = 30 + (u >> 3);
    } else {
        int t = bx - 96;                        // 0..479
        half = t >= 240;
        int u = half ? t - 240 : t;            // 0..239
        qb = u >> 3; h = u & 7;
    }

    const int tid = threadIdx.x;
    const int lane = tid & 31, wid = tid >> 5;
    const int wn = wid & 3, wm = wid >> 2;     // 4 x 4 warp grid
    const int g = lane >> 2, q4 = lane & 3;

    uint32_t sbase = (uint32_t)__cvta_generic_to_shared(sm);
    uint32_t sKb = sbase + 8192 * 4, sVb = sbase + 16384 * 4;

    // split the key-block list: half 0 takes the first ceil(n/2) bits,
    // half 1 the rest. Masks always have >= PROT bits, so npairs >= 3.
    unsigned long long mb = d_maskbits[(size_t)h * NB + qb];
    int nbits = __popcll(mb);
    int n0 = (nbits + 1) >> 1;
    int npairs;
    if (half == 0) {
        npairs = n0;
    } else {
        npairs = nbits - n0;
        for (int i = 0; i < n0; i++) mb &= mb - 1;
    }

    int kb = __ffsll((long long)mb) - 1;
    mb &= mb - 1;
    int remaining = npairs - 1;

    if (tid < 128)
        sperm[tid] = perm_of(qb * POOL + tid) * (HEADS * HDIM) + h * HDIM;

    // K0 + V0 in flight
    {
        const uint32_t* gk = d_kf + (size_t)(h * NB + kb) * HBLK;
#pragma unroll
        for (int i = 0; i < 4; i++) { int u = tid + 512 * i; cp16(sKb + u * 16, gk + u * 4); }
        CP_COMMIT();
        const uint32_t* gv = d_vf + (size_t)(h * NB + kb) * HBLK;
#pragma unroll
        for (int i = 0; i < 4; i++) { int u = tid + 512 * i; cp16(sVb + u * 16, gv + u * 4); }
        CP_COMMIT();
    }
    int kb_next = remaining > 0 ? (__ffsll((long long)mb) - 1) : -1;

    // gather Q (128 x 128 -> fp16 A-frags), overlapping cp.async arrival
    __syncthreads();  // sperm ready
    {
        const float scale = 0.12751743f;       // 128^-0.5 * log2(e)
        const int dq = tid & 127, r0 = tid >> 7;   // r0 in 0..3
        __half* hQ = (__half*)sQ;
#pragma unroll 8
        for (int i = 0; i < 32; i++) {
            int r = r0 + 4 * i;
            hQ[idxAhf(r, dq)] = __float2half(qsrc[(size_t)sperm[r] + dq] * scale);
        }
    }

    float o[2][4][4];
#pragma unroll
    for (int m = 0; m < 2; m++)
#pragma unroll
        for (int n = 0; n < 4; n++)
#pragma unroll
            for (int r = 0; r < 4; r++) o[m][n][r] = 0.f;
    float lr[2][2] = {{0.f, 0.f}, {0.f, 0.f}};   // [m][g / g+8] partial row sums

    for (;;) {
        CP_WAIT1();          // K_i arrived (V_i may be in flight)
        __syncthreads();     // + Q STS visible on first iter

        // ---- S = Q K^T (warp tile 32 x 32) ----
        float sacc[2][4][4];
#pragma unroll
        for (int m = 0; m < 2; m++)
#pragma unroll
            for (int n = 0; n < 4; n++)
#pragma unroll
                for (int r = 0; r < 4; r++) sacc[m][n][r] = 0.f;
#pragma unroll 4
        for (int kt = 0; kt < 8; kt++) {
            uint32_t a[2][4];
#pragma unroll
            for (int m = 0; m < 2; m++)
                *(uint4*)a[m] = *(const uint4*)(sQ + ((kt * 8 + wm * 2 + m) * 32 + lane) * 4);
#pragma unroll
            for (int j = 0; j < 2; j++) {
                uint4 b = *(const uint4*)(sK + ((kt * 8 + wn * 2 + j) * 32 + lane) * 4);
#pragma unroll
                for (int m = 0; m < 2; m++) {
                    mma_f16(sacc[m][2 * j],     a[m], b.x, b.y);
                    mma_f16(sacc[m][2 * j + 1], a[m], b.z, b.w);
                }
            }
        }
        __syncthreads();     // K consumed

        // prefetch next K
        if (kb_next >= 0) {
            const uint32_t* gk2 = d_kf + (size_t)(h * NB + kb_next) * HBLK;
#pragma unroll
            for (int i = 0; i < 4; i++) { int u = tid + 512 * i; cp16(sKb + u * 16, gk2 + u * 4); }
        }
        CP_COMMIT();

        // ---- softmax (no max; S pre-scaled by log2e) -> P fp16 A-frags ----
#pragma unroll
        for (int m = 0; m < 2; m++)
#pragma unroll
            for (int j = 0; j < 2; j++) {
                float e0 = ex2f(sacc[m][2 * j][0]);
                float e1 = ex2f(sacc[m][2 * j][1]);
                float e2 = ex2f(sacc[m][2 * j][2]);
                float e3 = ex2f(sacc[m][2 * j][3]);
                float f0 = ex2f(sacc[m][2 * j + 1][0]);
                float f1 = ex2f(sacc[m][2 * j + 1][1]);
                float f2 = ex2f(sacc[m][2 * j + 1][2]);
                float f3 = ex2f(sacc[m][2 * j + 1][3]);
                lr[m][0] += e0 + e1 + f0 + f1;
                lr[m][1] += e2 + e3 + f2 + f3;
                uint4 w4;
                w4.x = pack_hf2(e0, e1);   // (row g,   k-half 0)
                w4.y = pack_hf2(e2, e3);   // (row g+8, k-half 0)
                w4.z = pack_hf2(f0, f1);   // (row g,   k-half 1)
                w4.w = pack_hf2(f2, f3);   // (row g+8, k-half 1)
                int kc = wn * 2 + j;
                *(uint4*)(sP + ((kc * 8 + wm * 2 + m) * 32 + lane) * 4) = w4;
            }

        CP_WAIT1();          // V_i arrived (next-K may be in flight)
        __syncthreads();     // V + P visible

        // ---- O += P V (warp tile 32 x 32) ----
#pragma unroll 4
        for (int kt = 0; kt < 8; kt++) {
            uint32_t a[2][4];
#pragma unroll
            for (int m = 0; m < 2; m++)
                *(uint4*)a[m] = *(const uint4*)(sP + ((kt * 8 + wm * 2 + m) * 32 + lane) * 4);
#pragma unroll
            for (int j = 0; j < 2; j++) {
                uint4 b = *(const uint4*)(sV + ((kt * 8 + wn * 2 + j) * 32 + lane) * 4);
#pragma unroll
                for (int m = 0; m < 2; m++) {
                    mma_f16(o[m][2 * j],     a[m], b.x, b.y);
                    mma_f16(o[m][2 * j + 1], a[m], b.z, b.w);
                }
            }
        }
        if (kb_next < 0) break;
        __syncthreads();     // sV and sP consumed

        // prefetch next V
        {
            const uint32_t* gv2 = d_vf + (size_t)(h * NB + kb_next) * HBLK;
#pragma unroll
            for (int i = 0; i < 4; i++) { int u = tid + 512 * i; cp16(sVb + u * 16, gv2 + u * 4); }
        }
        CP_COMMIT();
        mb &= mb - 1;
        remaining--;
        kb_next = remaining > 0 ? (__ffsll((long long)mb) - 1) : -1;
    }

    // ---- epilogue: reduce l across 4 wn warps, write UNNORMALIZED partials ----
#pragma unroll
    for (int m = 0; m < 2; m++)
#pragma unroll
        for (int hh = 0; hh < 2; hh++) {
            float s = lr[m][hh];
            s += __shfl_xor_sync(0xffffffffu, s, 1);
            s += __shfl_xor_sync(0xffffffffu, s, 2);
            if (q4 == 0)
                lsm[(wm * 32 + m * 16 + hh * 8 + g) * 4 + wn] = s;
        }
    __syncthreads();
    {
        int idx = qb * HEADS + h;
        float* po = d_po + ((size_t)(half * NB * HEADS) + idx) * (POOL * HDIM);
        float* pl = d_pl + ((size_t)(half * NB * HEADS) + idx) * POOL;
#pragma unroll
        for (int m = 0; m < 2; m++)
#pragma unroll
            for (int hh = 0; hh < 2; hh++) {
                int r = wm * 32 + m * 16 + hh * 8 + g;
                if (wn == 0 && q4 == 0)
                    pl[r] = lsm[r * 4] + lsm[r * 4 + 1] + lsm[r * 4 + 2] + lsm[r * 4 + 3];
#pragma unroll
                for (int n = 0; n < 4; n++) {
                    int c = wn * 32 + n * 8 + 2 * q4;
                    *(float2*)(po + r * HDIM + c) =
                        make_float2(o[m][n][hh * 2], o[m][n][hh * 2 + 1]);
                }
            }
    }
}

// ---------------- 4) combine halves, normalize, permuted store ------------
__global__ void __launch_bounds__(512, 2)
combine_k(float* __restrict__ out) {
    __shared__ int sperm[128];
    __shared__ float sinv[128];
    const int idx = blockIdx.x;               // qb*8 + h
    const int qb = idx >> 3, h = idx & 7;
    const int tid = threadIdx.x;
    if (tid < 128) {
        sperm[tid] = perm_of(qb * POOL + tid) * (HEADS * HDIM) + h * HDIM;
        sinv[tid] = 1.0f / (d_pl[(size_t)idx * POOL + tid]
                          + d_pl[((size_t)(NB * HEADS) + idx) * POOL + tid]);
    }
    __syncthreads();
    const float4* p0 = (const float4*)(d_po + (size_t)idx * (POOL * HDIM));
    const float4* p1 = (const float4*)(d_po + ((size_t)(NB * HEADS) + idx) * (POOL * HDIM));
    const int c4 = tid & 31, rw = tid >> 5;   // 32 float4-cols, 16 row groups
#pragma unroll
    for (int i = 0; i < 8; i++) {
        int r = rw + 16 * i;
        float4 a = p0[r * 32 + c4];
        float4 b = p1[r * 32 + c4];
        float inv = sinv[r];
        float4 res;
        res.x = (a.x + b.x) * inv;
        res.y = (a.y + b.y) * inv;
        res.z = (a.z + b.z) * inv;
        res.w = (a.w + b.w) * inv;
        *(float4*)(out + sperm[r] + c4 * 4) = res;
    }
}

// ---------------- launch ----------------
extern "C" void kernel_launch(void* const* d_in, const int* in_sizes, int n_in,
                              void* d_out, int out_size) {
    const float* q = (const float*)d_in[0];
    const float* k = (const float*)d_in[1];
    const float* v = (const float*)d_in[2];
    float* out = (float*)d_out;

    const int gsmem = HBLK * 4 + 512 * 4 + 128 * 4;
    cudaFuncSetAttribute(gather_k, cudaFuncAttributeMaxDynamicSharedMemorySize, gsmem);

    const int asmem = (32768 + 512 + 128) * 4;   // ~133 KB -> 1 CTA/SM, 16 warps
    cudaFuncSetAttribute(attn_k, cudaFuncAttributeMaxDynamicSharedMemorySize, asmem);

    gather_k<<<dim3(NB, HEADS, 3), 512, gsmem>>>(q, k, v);
    mask_k<<<dim3(NB, HEADS), 64>>>();
    attn_k<<<NB * HEADS * 2, 512, asmem>>>(q);
    combine_k<<<NB * HEADS, 512>>>(out);
}

// round 14
// speedup vs baseline: 1.5777x; 1.5777x over previous
#include <cuda_runtime.h>
#include <cuda_fp16.h>
#include <math.h>
#include <stdint.h>

// ---------------- problem constants ----------------
#define SEQ   4608
#define HEADS 8
#define HDIM  128
#define NB    36
#define POOL  128
#define FFLN  384
#define KEEP  4
#define PROT  6
#define HBLK  8192    // 128*128 fp16 elements = 8192 u32 per (head, block)
#define NHEAVY 6      // qb 30..35 are always-full rows (protected)

// ---------------- device scratch ----------------
__device__ uint32_t d_kf[HEADS * NB * HBLK];  // K B-frag fp16 (k=dim, n=token)
__device__ uint32_t d_vf[HEADS * NB * HBLK];  // V B-frag fp16 (k=token, n=dim)
__device__ float d_qp[HEADS * NB * HDIM];
__device__ float d_kp[HEADS * NB * HDIM];
__device__ unsigned long long d_maskbits[HEADS * NB];
__device__ float d_po[2 * NHEAVY * HEADS * POOL * HDIM];  // heavy partial O
__device__ float d_pl[2 * NHEAVY * HEADS * POOL];          // heavy partial sums

// qkv2 position j -> original token index (verified round 1)
__device__ __forceinline__ int perm_of(int j) {
    if (j < 3840) {
        int b = j >> 7, w = j & 127;
        int fn = b / 6, hn = (b % 6) / 3, wn = b % 3;
        int f2 = w >> 6, r = (w >> 3) & 7, c = w & 7;
        return FFLN + (fn * 2 + f2) * 384 + (hn * 8 + r) * 24 + (wn * 8 + c);
    } else if (j < 4224) {
        return j - 3840;
    } else {
        return j;
    }
}

__device__ __forceinline__ uint32_t pack_hf2(float lo, float hi) {
    uint32_t r;
    asm("cvt.rn.f16x2.f32 %0, %1, %2;" : "=r"(r) : "f"(hi), "f"(lo));
    return r;
}
__device__ __forceinline__ float ex2f(float x) {
    float y;
    asm("ex2.approx.ftz.f32 %0, %1;" : "=f"(y) : "f"(x));
    return y;
}

// fp16 m16n8k16 B-frag builder: kx = MMA k-index, nx = MMA n-index;
// adjacent 8-wide n-tiles paired into one uint4 slot.
// returns fp16 element index (u32 slot * 2 + half)
__device__ __forceinline__ int idxBhf(int kx, int nx) {
    int kc = kx >> 4, kk = kx & 15;
    int q4 = (kk >> 1) & 3, hk = kk >> 3, half = kk & 1;
    int np = nx >> 4, odd = (nx >> 3) & 1, g = nx & 7;
    int slot = ((kc * 8 + np) * 32 + g * 4 + q4) * 4 + odd * 2 + hk;
    return slot * 2 + half;
}
// fp16 m16n8k16 A-frag (Q/P, 128 rows): r = row (0..127), c = k-index (0..127)
__device__ __forceinline__ int idxAhf(int r, int c) {
    int slot = (((c >> 4) * 8 + (r >> 4)) * 32 + (r & 7) * 4 + ((c >> 1) & 3)) * 4
             + ((r >> 3) & 1) + (((c >> 3) & 1) << 1);
    return slot * 2 + (c & 1);
}

__device__ __forceinline__ void mma_f16(float c[4], const uint32_t a[4], uint32_t b0, uint32_t b1) {
    asm volatile(
        "mma.sync.aligned.m16n8k16.row.col.f32.f16.f16.f32 "
        "{%0,%1,%2,%3}, {%4,%5,%6,%7}, {%8,%9}, {%0,%1,%2,%3};\n"
        : "+f"(c[0]), "+f"(c[1]), "+f"(c[2]), "+f"(c[3])
        : "r"(a[0]), "r"(a[1]), "r"(a[2]), "r"(a[3]), "r"(b0), "r"(b1));
}

__device__ __forceinline__ void cp16(uint32_t s, const void* g) {
    asm volatile("cp.async.cg.shared.global [%0], [%1], 16;" :: "r"(s), "l"(g));
}
#define CP_COMMIT() asm volatile("cp.async.commit_group;")
#define CP_WAIT1()  asm volatile("cp.async.wait_group 1;")

// ---------------- 1) gather/permute K,V + pool q,k ------------------------
// grid (NB, HEADS, 3), 512 threads: z=0 q-pool, z=1 K frags + pool, z=2 V frags.
__global__ void gather_k(const float* __restrict__ q,
                         const float* __restrict__ k,
                         const float* __restrict__ v) {
    extern __shared__ uint32_t stg[];            // HBLK u32
    float* psm = (float*)(stg + HBLK);           // 512
    int* sperm = (int*)(psm + 512);              // 128
    const int bl = blockIdx.x, h = blockIdx.y, z = blockIdx.z;
    const int tid = threadIdx.x;
    const int d = tid & 127, t0 = tid >> 7;      // t0 in 0..3

    if (tid < 128)
        sperm[tid] = perm_of(bl * POOL + tid) * (HEADS * HDIM) + h * HDIM;
    __syncthreads();

    if (z == 0) {
        float part = 0.f;
#pragma unroll 16
        for (int i = 0; i < 32; i++) part += q[(size_t)sperm[t0 + 4 * i] + d];
        psm[tid] = part;
        __syncthreads();
        if (tid < 128)
            d_qp[(size_t)(h * NB + bl) * HDIM + tid] =
                (psm[tid] + psm[tid + 128] + psm[tid + 256] + psm[tid + 384])
                * (1.0f / POOL);
    } else if (z == 1) {
        __half* hstg = (__half*)stg;
        float part = 0.f;
#pragma unroll 16
        for (int i = 0; i < 32; i++) {
            int t = t0 + 4 * i;
            float val = k[(size_t)sperm[t] + d];
            part += val;
            hstg[idxBhf(d, t)] = __float2half(val);   // k-index = dim, n = token
        }
        psm[tid] = part;
        __syncthreads();
        uint4* dst = (uint4*)(d_kf + (size_t)(h * NB + bl) * HBLK);
        const uint4* src = (const uint4*)stg;
#pragma unroll
        for (int i = 0; i < 4; i++) dst[tid + 512 * i] = src[tid + 512 * i];
        if (tid < 128)
            d_kp[(size_t)(h * NB + bl) * HDIM + tid] =
                (psm[tid] + psm[tid + 128] + psm[tid + 256] + psm[tid + 384])
                * (1.0f / POOL);
    } else {
        __half* hstg = (__half*)stg;
#pragma unroll 16
        for (int i = 0; i < 32; i++) {
            int t = t0 + 4 * i;
            hstg[idxBhf(t, d)] = __float2half(v[(size_t)sperm[t] + d]);  // k = token, n = dim
        }
        __syncthreads();
        uint4* dst = (uint4*)(d_vf + (size_t)(h * NB + bl) * HBLK);
        const uint4* src = (const uint4*)stg;
#pragma unroll
        for (int i = 0; i < 4; i++) dst[tid + 512 * i] = src[tid + 512 * i];
    }
}

// ---------------- 2) top-4 threshold -> block mask ------------------------
__global__ void mask_k() {
    int l = blockIdx.x, h = blockIdx.y;
    __shared__ float lg[NB];
    int s = threadIdx.x;
    if (s < NB) {
        const float* qv = d_qp + ((size_t)h * NB + l) * HDIM;
        const float* kv = d_kp + ((size_t)h * NB + s) * HDIM;
        float acc = 0.f;
        for (int t = 0; t < HDIM; t++) acc += qv[t] * kv[t];
        lg[s] = acc;
    }
    __syncthreads();
    if (threadIdx.x == 0) {
        float vals[NB];
        for (int i = 0; i < NB; i++) vals[i] = lg[i];
        float thr = 0.f;
        for (int it = 0; it < KEEP; it++) {
            int bi = 0; float bv = -INFINITY;
            for (int i = 0; i < NB; i++) if (vals[i] > bv) { bv = vals[i]; bi = i; }
            thr = bv; vals[bi] = -INFINITY;
        }
        unsigned long long m = 0;
        for (int i = 0; i < NB; i++) if (lg[i] >= thr) m |= 1ull << i;
        m |= ((1ull << PROT) - 1ull) << (NB - PROT);
        if (l >= NB - PROT) m = (1ull << NB) - 1ull;
        d_maskbits[(size_t)h * NB + l] = m;
    }
}

// ---------------- 3) all-fp16 attention; heavy rows split in two ----------
// 336 CTAs: bx<96 = heavy halves (qb 30..35, 18 key blocks each, write
// unnormalized partials); bx>=96 = whole light CTAs (direct store).
// 512 threads, 4x4 warp grid, warp tile 32x32. No-max softmax.
__global__ void __launch_bounds__(512, 1)
attn_k(const float* __restrict__ qsrc, float* __restrict__ out) {
    extern __shared__ uint32_t sm[];
    uint32_t* sQ = sm;                         // 8192 (32KB) fp16 A-frags
    uint32_t* sK = sm + 8192;                  // 8192 (32KB) fp16 B-frags
    uint32_t* sV = sm + 16384;                 // 8192 (32KB) fp16 B-frags
    uint32_t* sP = sm + 24576;                 // 8192 (32KB) fp16 A-frags
    float* lsm = (float*)(sm + 32768);         // 128 x 4
    int* sperm = (int*)(lsm + 512);            // 128

    int bx = blockIdx.x;
    int qb, h, half = 0;
    bool split;
    if (bx < 96) {                             // heavy halves first
        split = true;
        half = bx & 1;
        int u = bx >> 1;                       // 0..47
        h = u & 7; qb = 30 + (u >> 3);
    } else {
        split = false;
        int t = bx - 96;                       // 0..239
        qb = t >> 3; h = t & 7;
    }

    const int tid = threadIdx.x;
    const int lane = tid & 31, wid = tid >> 5;
    const int wn = wid & 3, wm = wid >> 2;     // 4 x 4 warp grid
    const int g = lane >> 2, q4 = lane & 3;

    uint32_t sbase = (uint32_t)__cvta_generic_to_shared(sm);
    uint32_t sKb = sbase + 8192 * 4, sVb = sbase + 16384 * 4;

    unsigned long long mb = d_maskbits[(size_t)h * NB + qb];
    int npairs = __popcll(mb);
    if (split) {
        int n0 = (npairs + 1) >> 1;            // heavy masks are full: 18/18
        if (half == 0) {
            npairs = n0;
        } else {
            npairs -= n0;
            for (int i = 0; i < n0; i++) mb &= mb - 1;
        }
    }

    int kb = __ffsll((long long)mb) - 1;
    mb &= mb - 1;
    int remaining = npairs - 1;

    if (tid < 128)
        sperm[tid] = perm_of(qb * POOL + tid) * (HEADS * HDIM) + h * HDIM;

    // K0 + V0 in flight
    {
        const uint32_t* gk = d_kf + (size_t)(h * NB + kb) * HBLK;
#pragma unroll
        for (int i = 0; i < 4; i++) { int u = tid + 512 * i; cp16(sKb + u * 16, gk + u * 4); }
        CP_COMMIT();
        const uint32_t* gv = d_vf + (size_t)(h * NB + kb) * HBLK;
#pragma unroll
        for (int i = 0; i < 4; i++) { int u = tid + 512 * i; cp16(sVb + u * 16, gv + u * 4); }
        CP_COMMIT();
    }
    int kb_next = remaining > 0 ? (__ffsll((long long)mb) - 1) : -1;

    // gather Q (128 x 128 -> fp16 A-frags), overlapping cp.async arrival
    __syncthreads();  // sperm ready
    {
        const float scale = 0.12751743f;       // 128^-0.5 * log2(e)
        const int dq = tid & 127, r0 = tid >> 7;   // r0 in 0..3
        __half* hQ = (__half*)sQ;
#pragma unroll 8
        for (int i = 0; i < 32; i++) {
            int r = r0 + 4 * i;
            hQ[idxAhf(r, dq)] = __float2half(qsrc[(size_t)sperm[r] + dq] * scale);
        }
    }

    float o[2][4][4];
#pragma unroll
    for (int m = 0; m < 2; m++)
#pragma unroll
        for (int n = 0; n < 4; n++)
#pragma unroll
            for (int r = 0; r < 4; r++) o[m][n][r] = 0.f;
    float lr[2][2] = {{0.f, 0.f}, {0.f, 0.f}};   // [m][g / g+8] partial row sums

    for (;;) {
        CP_WAIT1();          // K_i arrived (V_i may be in flight)
        __syncthreads();     // + Q STS visible on first iter

        // ---- S = Q K^T (warp tile 32 x 32) ----
        float sacc[2][4][4];
#pragma unroll
        for (int m = 0; m < 2; m++)
#pragma unroll
            for (int n = 0; n < 4; n++)
#pragma unroll
                for (int r = 0; r < 4; r++) sacc[m][n][r] = 0.f;
#pragma unroll 4
        for (int kt = 0; kt < 8; kt++) {
            uint32_t a[2][4];
#pragma unroll
            for (int m = 0; m < 2; m++)
                *(uint4*)a[m] = *(const uint4*)(sQ + ((kt * 8 + wm * 2 + m) * 32 + lane) * 4);
#pragma unroll
            for (int j = 0; j < 2; j++) {
                uint4 b = *(const uint4*)(sK + ((kt * 8 + wn * 2 + j) * 32 + lane) * 4);
#pragma unroll
                for (int m = 0; m < 2; m++) {
                    mma_f16(sacc[m][2 * j],     a[m], b.x, b.y);
                    mma_f16(sacc[m][2 * j + 1], a[m], b.z, b.w);
                }
            }
        }
        __syncthreads();     // K consumed

        // prefetch next K
        if (kb_next >= 0) {
            const uint32_t* gk2 = d_kf + (size_t)(h * NB + kb_next) * HBLK;
#pragma unroll
            for (int i = 0; i < 4; i++) { int u = tid + 512 * i; cp16(sKb + u * 16, gk2 + u * 4); }
        }
        CP_COMMIT();

        // ---- softmax (no max; S pre-scaled by log2e) -> P fp16 A-frags ----
#pragma unroll
        for (int m = 0; m < 2; m++)
#pragma unroll
            for (int j = 0; j < 2; j++) {
                float e0 = ex2f(sacc[m][2 * j][0]);
                float e1 = ex2f(sacc[m][2 * j][1]);
                float e2 = ex2f(sacc[m][2 * j][2]);
                float e3 = ex2f(sacc[m][2 * j][3]);
                float f0 = ex2f(sacc[m][2 * j + 1][0]);
                float f1 = ex2f(sacc[m][2 * j + 1][1]);
                float f2 = ex2f(sacc[m][2 * j + 1][2]);
                float f3 = ex2f(sacc[m][2 * j + 1][3]);
                lr[m][0] += e0 + e1 + f0 + f1;
                lr[m][1] += e2 + e3 + f2 + f3;
                uint4 w4;
                w4.x = pack_hf2(e0, e1);   // (row g,   k-half 0)
                w4.y = pack_hf2(e2, e3);   // (row g+8, k-half 0)
                w4.z = pack_hf2(f0, f1);   // (row g,   k-half 1)
                w4.w = pack_hf2(f2, f3);   // (row g+8, k-half 1)
                int kc = wn * 2 + j;
                *(uint4*)(sP + ((kc * 8 + wm * 2 + m) * 32 + lane) * 4) = w4;
            }

        CP_WAIT1();          // V_i arrived (next-K may be in flight)
        __syncthreads();     // V + P visible

        // ---- O += P V (warp tile 32 x 32) ----
#pragma unroll 4
        for (int kt = 0; kt < 8; kt++) {
            uint32_t a[2][4];
#pragma unroll
            for (int m = 0; m < 2; m++)
                *(uint4*)a[m] = *(const uint4*)(sP + ((kt * 8 + wm * 2 + m) * 32 + lane) * 4);
#pragma unroll
            for (int j = 0; j < 2; j++) {
                uint4 b = *(const uint4*)(sV + ((kt * 8 + wn * 2 + j) * 32 + lane) * 4);
#pragma unroll
                for (int m = 0; m < 2; m++) {
                    mma_f16(o[m][2 * j],     a[m], b.x, b.y);
                    mma_f16(o[m][2 * j + 1], a[m], b.z, b.w);
                }
            }
        }
        if (kb_next < 0) break;
        __syncthreads();     // sV and sP consumed

        // prefetch next V
        {
            const uint32_t* gv2 = d_vf + (size_t)(h * NB + kb_next) * HBLK;
#pragma unroll
            for (int i = 0; i < 4; i++) { int u = tid + 512 * i; cp16(sVb + u * 16, gv2 + u * 4); }
        }
        CP_COMMIT();
        mb &= mb - 1;
        remaining--;
        kb_next = remaining > 0 ? (__ffsll((long long)mb) - 1) : -1;
    }

    // ---- epilogue: reduce l across 4 wn warps ----
#pragma unroll
    for (int m = 0; m < 2; m++)
#pragma unroll
        for (int hh = 0; hh < 2; hh++) {
            float s = lr[m][hh];
            s += __shfl_xor_sync(0xffffffffu, s, 1);
            s += __shfl_xor_sync(0xffffffffu, s, 2);
            if (q4 == 0)
                lsm[(wm * 32 + m * 16 + hh * 8 + g) * 4 + wn] = s;
        }
    __syncthreads();

    if (split) {
        // heavy half: write UNNORMALIZED partials
        int idx = (qb - 30) * HEADS + h;
        float* po = d_po + ((size_t)(half * NHEAVY * HEADS) + idx) * (POOL * HDIM);
        float* pl = d_pl + ((size_t)(half * NHEAVY * HEADS) + idx) * POOL;
#pragma unroll
        for (int m = 0; m < 2; m++)
#pragma unroll
            for (int hh = 0; hh < 2; hh++) {
                int r = wm * 32 + m * 16 + hh * 8 + g;
                if (wn == 0 && q4 == 0)
                    pl[r] = lsm[r * 4] + lsm[r * 4 + 1] + lsm[r * 4 + 2] + lsm[r * 4 + 3];
#pragma unroll
                for (int n = 0; n < 4; n++) {
                    int c = wn * 32 + n * 8 + 2 * q4;
                    *(float2*)(po + r * HDIM + c) =
                        make_float2(o[m][n][hh * 2], o[m][n][hh * 2 + 1]);
                }
            }
    } else {
        // light CTA: normalize and permuted-store directly
#pragma unroll
        for (int m = 0; m < 2; m++)
#pragma unroll
            for (int hh = 0; hh < 2; hh++) {
                int r = wm * 32 + m * 16 + hh * 8 + g;
                float inv = 1.0f / (lsm[r * 4] + lsm[r * 4 + 1] + lsm[r * 4 + 2] + lsm[r * 4 + 3]);
                float* og = out + sperm[r];
#pragma unroll
                for (int n = 0; n < 4; n++) {
                    int c = wn * 32 + n * 8 + 2 * q4;
                    *(float2*)(og + c) = make_float2(o[m][n][hh * 2] * inv,
                                                     o[m][n][hh * 2 + 1] * inv);
                }
            }
    }
}

// ---------------- 4) combine heavy halves, normalize, permuted store ------
__global__ void __launch_bounds__(512, 2)
combine_k(float* __restrict__ out) {
    __shared__ int sperm[128];
    __shared__ float sinv[128];
    const int idx = blockIdx.x;               // (qb-30)*8 + h, 0..47
    const int qb = 30 + (idx >> 3), h = idx & 7;
    const int tid = threadIdx.x;
    if (tid < 128) {
        sperm[tid] = perm_of(qb * POOL + tid) * (HEADS * HDIM) + h * HDIM;
        sinv[tid] = 1.0f / (d_pl[(size_t)idx * POOL + tid]
                          + d_pl[((size_t)(NHEAVY * HEADS) + idx) * POOL + tid]);
    }
    __syncthreads();
    const float4* p0 = (const float4*)(d_po + (size_t)idx * (POOL * HDIM));
    const float4* p1 = (const float4*)(d_po + ((size_t)(NHEAVY * HEADS) + idx) * (POOL * HDIM));
    const int c4 = tid & 31, rw = tid >> 5;   // 32 float4-cols, 16 row groups
#pragma unroll
    for (int i = 0; i < 8; i++) {
        int r = rw + 16 * i;
        float4 a = p0[r * 32 + c4];
        float4 b = p1[r * 32 + c4];
        float inv = sinv[r];
        float4 res;
        res.x = (a.x + b.x) * inv;
        res.y = (a.y + b.y) * inv;
        res.z = (a.z + b.z) * inv;
        res.w = (a.w + b.w) * inv;
        *(float4*)(out + sperm[r] + c4 * 4) = res;
    }
}

// ---------------- launch ----------------
extern "C" void kernel_launch(void* const* d_in, const int* in_sizes, int n_in,
                              void* d_out, int out_size) {
    const float* q = (const float*)d_in[0];
    const float* k = (const float*)d_in[1];
    const float* v = (const float*)d_in[2];
    float* out = (float*)d_out;

    const int gsmem = HBLK * 4 + 512 * 4 + 128 * 4;
    cudaFuncSetAttribute(gather_k, cudaFuncAttributeMaxDynamicSharedMemorySize, gsmem);

    const int asmem = (32768 + 512 + 128) * 4;   // ~133 KB -> 1 CTA/SM, 16 warps
    cudaFuncSetAttribute(attn_k, cudaFuncAttributeMaxDynamicSharedMemorySize, asmem);

    gather_k<<<dim3(NB, HEADS, 3), 512, gsmem>>>(q, k, v);
    mask_k<<<dim3(NB, HEADS), 64>>>();
    attn_k<<<96 + (NB - NHEAVY) * HEADS, 512, asmem>>>(q, out);
    combine_k<<<NHEAVY * HEADS, 512>>>(out);
}

// round 15
// speedup vs baseline: 1.6978x; 1.0761x over previous
#include <cuda_runtime.h>
#include <cuda_fp16.h>
#include <math.h>
#include <stdint.h>

// ---------------- problem constants ----------------
#define SEQ   4608
#define HEADS 8
#define HDIM  128
#define NB    36
#define POOL  128
#define FFLN  384
#define KEEP  4
#define PROT  6
#define HBLK  8192    // 128*128 fp16 elements = 8192 u32 per (head, block)

// ---------------- device scratch ----------------
__device__ uint32_t d_kf[HEADS * NB * HBLK];  // K B-frag fp16 (k=dim, n=token)
__device__ uint32_t d_vf[HEADS * NB * HBLK];  // V B-frag fp16 (k=token, n=dim)
__device__ float d_qp[HEADS * NB * HDIM];
__device__ float d_kp[HEADS * NB * HDIM];
__device__ unsigned long long d_maskbits[HEADS * NB];

// qkv2 position j -> original token index (verified round 1)
__device__ __forceinline__ int perm_of(int j) {
    if (j < 3840) {
        int b = j >> 7, w = j & 127;
        int fn = b / 6, hn = (b % 6) / 3, wn = b % 3;
        int f2 = w >> 6, r = (w >> 3) & 7, c = w & 7;
        return FFLN + (fn * 2 + f2) * 384 + (hn * 8 + r) * 24 + (wn * 8 + c);
    } else if (j < 4224) {
        return j - 3840;
    } else {
        return j;
    }
}

__device__ __forceinline__ uint32_t pack_hf2(float lo, float hi) {
    uint32_t r;
    asm("cvt.rn.f16x2.f32 %0, %1, %2;" : "=r"(r) : "f"(hi), "f"(lo));
    return r;
}
__device__ __forceinline__ float ex2f(float x) {
    float y;
    asm("ex2.approx.ftz.f32 %0, %1;" : "=f"(y) : "f"(x));
    return y;
}

// fp16 m16n8k16 B-frag builder: kx = MMA k-index, nx = MMA n-index;
// adjacent 8-wide n-tiles paired into one uint4 slot.
// returns fp16 element index (u32 slot * 2 + half)
__device__ __forceinline__ int idxBhf(int kx, int nx) {
    int kc = kx >> 4, kk = kx & 15;
    int q4 = (kk >> 1) & 3, hk = kk >> 3, half = kk & 1;
    int np = nx >> 4, odd = (nx >> 3) & 1, g = nx & 7;
    int slot = ((kc * 8 + np) * 32 + g * 4 + q4) * 4 + odd * 2 + hk;
    return slot * 2 + half;
}
// fp16 m16n8k16 A-frag (Q/P, 128 rows): r = row (0..127), c = k-index (0..127)
__device__ __forceinline__ int idxAhf(int r, int c) {
    int slot = (((c >> 4) * 8 + (r >> 4)) * 32 + (r & 7) * 4 + ((c >> 1) & 3)) * 4
             + ((r >> 3) & 1) + (((c >> 3) & 1) << 1);
    return slot * 2 + (c & 1);
}

__device__ __forceinline__ void mma_f16(float c[4], const uint32_t a[4], uint32_t b0, uint32_t b1) {
    asm volatile(
        "mma.sync.aligned.m16n8k16.row.col.f32.f16.f16.f32 "
        "{%0,%1,%2,%3}, {%4,%5,%6,%7}, {%8,%9}, {%0,%1,%2,%3};\n"
        : "+f"(c[0]), "+f"(c[1]), "+f"(c[2]), "+f"(c[3])
        : "r"(a[0]), "r"(a[1]), "r"(a[2]), "r"(a[3]), "r"(b0), "r"(b1));
}

__device__ __forceinline__ void cp16(uint32_t s, const void* g) {
    asm volatile("cp.async.cg.shared.global [%0], [%1], 16;" :: "r"(s), "l"(g));
}
#define CP_COMMIT() asm volatile("cp.async.commit_group;")
#define CP_WAIT0()  asm volatile("cp.async.wait_group 0;")

// ---------------- 1) gather/permute K,V + pool q,k ------------------------
// grid (NB, HEADS, 3), 512 threads: z=0 q-pool, z=1 K frags + pool, z=2 V frags.
__global__ void gather_k(const float* __restrict__ q,
                         const float* __restrict__ k,
                         const float* __restrict__ v) {
    extern __shared__ uint32_t stg[];            // HBLK u32
    float* psm = (float*)(stg + HBLK);           // 512
    int* sperm = (int*)(psm + 512);              // 128
    const int bl = blockIdx.x, h = blockIdx.y, z = blockIdx.z;
    const int tid = threadIdx.x;
    const int d = tid & 127, t0 = tid >> 7;      // t0 in 0..3

    if (tid < 128)
        sperm[tid] = perm_of(bl * POOL + tid) * (HEADS * HDIM) + h * HDIM;
    __syncthreads();

    if (z == 0) {
        float part = 0.f;
#pragma unroll 16
        for (int i = 0; i < 32; i++) part += q[(size_t)sperm[t0 + 4 * i] + d];
        psm[tid] = part;
        __syncthreads();
        if (tid < 128)
            d_qp[(size_t)(h * NB + bl) * HDIM + tid] =
                (psm[tid] + psm[tid + 128] + psm[tid + 256] + psm[tid + 384])
                * (1.0f / POOL);
    } else if (z == 1) {
        __half* hstg = (__half*)stg;
        float part = 0.f;
#pragma unroll 16
        for (int i = 0; i < 32; i++) {
            int t = t0 + 4 * i;
            float val = k[(size_t)sperm[t] + d];
            part += val;
            hstg[idxBhf(d, t)] = __float2half(val);   // k-index = dim, n = token
        }
        psm[tid] = part;
        __syncthreads();
        uint4* dst = (uint4*)(d_kf + (size_t)(h * NB + bl) * HBLK);
        const uint4* src = (const uint4*)stg;
#pragma unroll
        for (int i = 0; i < 4; i++) dst[tid + 512 * i] = src[tid + 512 * i];
        if (tid < 128)
            d_kp[(size_t)(h * NB + bl) * HDIM + tid] =
                (psm[tid] + psm[tid + 128] + psm[tid + 256] + psm[tid + 384])
                * (1.0f / POOL);
    } else {
        __half* hstg = (__half*)stg;
#pragma unroll 16
        for (int i = 0; i < 32; i++) {
            int t = t0 + 4 * i;
            hstg[idxBhf(t, d)] = __float2half(v[(size_t)sperm[t] + d]);  // k = token, n = dim
        }
        __syncthreads();
        uint4* dst = (uint4*)(d_vf + (size_t)(h * NB + bl) * HBLK);
        const uint4* src = (const uint4*)stg;
#pragma unroll
        for (int i = 0; i < 4; i++) dst[tid + 512 * i] = src[tid + 512 * i];
    }
}

// ---------------- 2) top-4 threshold -> block mask ------------------------
__global__ void mask_k() {
    int l = blockIdx.x, h = blockIdx.y;
    __shared__ float lg[NB];
    int s = threadIdx.x;
    if (s < NB) {
        const float* qv = d_qp + ((size_t)h * NB + l) * HDIM;
        const float* kv = d_kp + ((size_t)h * NB + s) * HDIM;
        float acc = 0.f;
        for (int t = 0; t < HDIM; t++) acc += qv[t] * kv[t];
        lg[s] = acc;
    }
    __syncthreads();
    if (threadIdx.x == 0) {
        float vals[NB];
        for (int i = 0; i < NB; i++) vals[i] = lg[i];
        float thr = 0.f;
        for (int it = 0; it < KEEP; it++) {
            int bi = 0; float bv = -INFINITY;
            for (int i = 0; i < NB; i++) if (vals[i] > bv) { bv = vals[i]; bi = i; }
            thr = bv; vals[bi] = -INFINITY;
        }
        unsigned long long m = 0;
        for (int i = 0; i < NB; i++) if (lg[i] >= thr) m |= 1ull << i;
        m |= ((1ull << PROT) - 1ull) << (NB - PROT);
        if (l >= NB - PROT) m = (1ull << NB) - 1ull;
        d_maskbits[(size_t)h * NB + l] = m;
    }
}

// ---------------- 3) all-fp16 attention, double-buffered K/V --------------
// One CTA per (qblock, head); 512 threads, 4x4 warp grid, warp tile 32x32.
// K and V double-buffered: prefetch of pair i+1 issued at TOP of iter i
// (full-iteration lead). Only 2 barriers/iter: BAR1 (arrival + prev-iter
// completion -> alt buffers and sP provably free), BAR2 (P visibility).
__global__ void __launch_bounds__(512, 1)
attn_k(const float* __restrict__ qsrc, float* __restrict__ out) {
    extern __shared__ uint32_t sm[];
    uint32_t* sQ = sm;                          // 8192  (32KB) fp16 A-frags
    uint32_t* sKbuf = sm + 8192;                // 2 x 8192 (64KB)
    uint32_t* sVbuf = sm + 24576;               // 2 x 8192 (64KB)
    uint32_t* sP = sm + 40960;                  // 8192  (32KB) fp16 A-frags
    float* lsm = (float*)(sm + 49152);          // 128 x 4
    int* sperm = (int*)(lsm + 512);             // 128

    // heavy-first ordering: qb 30..35 first
    int bx = blockIdx.x;
    int qb, h;
    if (bx < 48) { qb = 30 + (bx >> 3); h = bx & 7; }
    else         { int t = bx - 48; qb = t >> 3; h = t & 7; }

    const int tid = threadIdx.x;
    const int lane = tid & 31, wid = tid >> 5;
    const int wn = wid & 3, wm = wid >> 2;      // 4 x 4 warp grid
    const int g = lane >> 2, q4 = lane & 3;

    uint32_t sbase = (uint32_t)__cvta_generic_to_shared(sm);
    uint32_t sKb0 = sbase + 8192 * 4, sVb0 = sbase + 24576 * 4;

    unsigned long long mb = d_maskbits[(size_t)h * NB + qb];
    int kb = __ffsll((long long)mb) - 1;
    mb &= mb - 1;

    if (tid < 128)
        sperm[tid] = perm_of(qb * POOL + tid) * (HEADS * HDIM) + h * HDIM;

    // issue K0 + V0 into buffer 0 (one group)
    {
        const uint32_t* gk = d_kf + (size_t)(h * NB + kb) * HBLK;
        const uint32_t* gv = d_vf + (size_t)(h * NB + kb) * HBLK;
#pragma unroll
        for (int i = 0; i < 4; i++) { int u = tid + 512 * i; cp16(sKb0 + u * 16, gk + u * 4); }
#pragma unroll
        for (int i = 0; i < 4; i++) { int u = tid + 512 * i; cp16(sVb0 + u * 16, gv + u * 4); }
        CP_COMMIT();
    }
    int kb_next = mb ? (__ffsll((long long)mb) - 1) : -1;

    // gather Q (128 x 128 -> fp16 A-frags), overlapping cp.async arrival
    __syncthreads();  // sperm ready
    {
        const float scale = 0.12751743f;        // 128^-0.5 * log2(e)
        const int dq = tid & 127, r0 = tid >> 7;
        __half* hQ = (__half*)sQ;
#pragma unroll 8
        for (int i = 0; i < 32; i++) {
            int r = r0 + 4 * i;
            hQ[idxAhf(r, dq)] = __float2half(qsrc[(size_t)sperm[r] + dq] * scale);
        }
    }

    float o[2][4][4];
#pragma unroll
    for (int m = 0; m < 2; m++)
#pragma unroll
        for (int n = 0; n < 4; n++)
#pragma unroll
            for (int r = 0; r < 4; r++) o[m][n][r] = 0.f;
    float lr[2][2] = {{0.f, 0.f}, {0.f, 0.f}};

    int buf = 0;
    for (;;) {
        CP_WAIT0();          // K_i + V_i arrived (issued a full iteration ago)
        __syncthreads();     // BAR1: arrivals visible; all warps done prev iter
                             // -> alt K/V buffers and sP are free

        // issue prefetch of pair i+1 into the alternate buffers
        if (kb_next >= 0) {
            const uint32_t* gk2 = d_kf + (size_t)(h * NB + kb_next) * HBLK;
            const uint32_t* gv2 = d_vf + (size_t)(h * NB + kb_next) * HBLK;
            uint32_t ka = sKb0 + (buf ^ 1) * 8192 * 4;
            uint32_t va = sVb0 + (buf ^ 1) * 8192 * 4;
#pragma unroll
            for (int i = 0; i < 4; i++) { int u = tid + 512 * i; cp16(ka + u * 16, gk2 + u * 4); }
#pragma unroll
            for (int i = 0; i < 4; i++) { int u = tid + 512 * i; cp16(va + u * 16, gv2 + u * 4); }
        }
        CP_COMMIT();

        const uint32_t* sK = sKbuf + buf * 8192;
        const uint32_t* sV = sVbuf + buf * 8192;

        // ---- S = Q K^T (warp tile 32 x 32) ----
        float sacc[2][4][4];
#pragma unroll
        for (int m = 0; m < 2; m++)
#pragma unroll
            for (int n = 0; n < 4; n++)
#pragma unroll
                for (int r = 0; r < 4; r++) sacc[m][n][r] = 0.f;
#pragma unroll 4
        for (int kt = 0; kt < 8; kt++) {
            uint32_t a[2][4];
#pragma unroll
            for (int m = 0; m < 2; m++)
                *(uint4*)a[m] = *(const uint4*)(sQ + ((kt * 8 + wm * 2 + m) * 32 + lane) * 4);
#pragma unroll
            for (int j = 0; j < 2; j++) {
                uint4 b = *(const uint4*)(sK + ((kt * 8 + wn * 2 + j) * 32 + lane) * 4);
#pragma unroll
                for (int m = 0; m < 2; m++) {
                    mma_f16(sacc[m][2 * j],     a[m], b.x, b.y);
                    mma_f16(sacc[m][2 * j + 1], a[m], b.z, b.w);
                }
            }
        }

        // ---- softmax (no max; S pre-scaled by log2e) -> P fp16 A-frags ----
#pragma unroll
        for (int m = 0; m < 2; m++)
#pragma unroll
            for (int j = 0; j < 2; j++) {
                float e0 = ex2f(sacc[m][2 * j][0]);
                float e1 = ex2f(sacc[m][2 * j][1]);
                float e2 = ex2f(sacc[m][2 * j][2]);
                float e3 = ex2f(sacc[m][2 * j][3]);
                float f0 = ex2f(sacc[m][2 * j + 1][0]);
                float f1 = ex2f(sacc[m][2 * j + 1][1]);
                float f2 = ex2f(sacc[m][2 * j + 1][2]);
                float f3 = ex2f(sacc[m][2 * j + 1][3]);
                lr[m][0] += e0 + e1 + f0 + f1;
                lr[m][1] += e2 + e3 + f2 + f3;
                uint4 w4;
                w4.x = pack_hf2(e0, e1);
                w4.y = pack_hf2(e2, e3);
                w4.z = pack_hf2(f0, f1);
                w4.w = pack_hf2(f2, f3);
                int kc = wn * 2 + j;
                *(uint4*)(sP + ((kc * 8 + wm * 2 + m) * 32 + lane) * 4) = w4;
            }

        __syncthreads();     // BAR2: P visible to all warps

        // ---- O += P V (warp tile 32 x 32) ----
#pragma unroll 4
        for (int kt = 0; kt < 8; kt++) {
            uint32_t a[2][4];
#pragma unroll
            for (int m = 0; m < 2; m++)
                *(uint4*)a[m] = *(const uint4*)(sP + ((kt * 8 + wm * 2 + m) * 32 + lane) * 4);
#pragma unroll
            for (int j = 0; j < 2; j++) {
                uint4 b = *(const uint4*)(sV + ((kt * 8 + wn * 2 + j) * 32 + lane) * 4);
#pragma unroll
                for (int m = 0; m < 2; m++) {
                    mma_f16(o[m][2 * j],     a[m], b.x, b.y);
                    mma_f16(o[m][2 * j + 1], a[m], b.z, b.w);
                }
            }
        }
        if (kb_next < 0) break;
        mb &= mb - 1;
        kb = kb_next;
        kb_next = mb ? (__ffsll((long long)mb) - 1) : -1;
        buf ^= 1;
    }

    // ---- epilogue: reduce l across 4 wn warps, normalize, permuted store ----
#pragma unroll
    for (int m = 0; m < 2; m++)
#pragma unroll
        for (int hh = 0; hh < 2; hh++) {
            float s = lr[m][hh];
            s += __shfl_xor_sync(0xffffffffu, s, 1);
            s += __shfl_xor_sync(0xffffffffu, s, 2);
            if (q4 == 0)
                lsm[(wm * 32 + m * 16 + hh * 8 + g) * 4 + wn] = s;
        }
    __syncthreads();
#pragma unroll
    for (int m = 0; m < 2; m++)
#pragma unroll
        for (int hh = 0; hh < 2; hh++) {
            int r = wm * 32 + m * 16 + hh * 8 + g;
            float inv = 1.0f / (lsm[r * 4] + lsm[r * 4 + 1] + lsm[r * 4 + 2] + lsm[r * 4 + 3]);
            float* og = out + sperm[r];
#pragma unroll
            for (int n = 0; n < 4; n++) {
                int c = wn * 32 + n * 8 + 2 * q4;
                *(float2*)(og + c) = make_float2(o[m][n][hh * 2] * inv,
                                                 o[m][n][hh * 2 + 1] * inv);
            }
        }
}

// ---------------- launch ----------------
extern "C" void kernel_launch(void* const* d_in, const int* in_sizes, int n_in,
                              void* d_out, int out_size) {
    const float* q = (const float*)d_in[0];
    const float* k = (const float*)d_in[1];
    const float* v = (const float*)d_in[2];
    float* out = (float*)d_out;

    const int gsmem = HBLK * 4 + 512 * 4 + 128 * 4;
    cudaFuncSetAttribute(gather_k, cudaFuncAttributeMaxDynamicSharedMemorySize, gsmem);

    const int asmem = (49152 + 512 + 128) * 4;   // ~195 KB -> 1 CTA/SM
    cudaFuncSetAttribute(attn_k, cudaFuncAttributeMaxDynamicSharedMemorySize, asmem);

    gather_k<<<dim3(NB, HEADS, 3), 512, gsmem>>>(q, k, v);
    mask_k<<<dim3(NB, HEADS), 64>>>();
    attn_k<<<NB * HEADS, 512, asmem>>>(q, out);
}

// round 17
// speedup vs baseline: 1.7691x; 1.0420x over previous
#include <cuda_runtime.h>
#include <cuda_fp16.h>
#include <math.h>
#include <stdint.h>

// ---------------- problem constants ----------------
#define SEQ   4608
#define HEADS 8
#define HDIM  128
#define NB    36
#define POOL  128
#define FFLN  384
#define KEEP  4
#define PROT  6
#define HBLK  8192    // 128*128 fp16 elements = 8192 u32 per (head, block)

// ---------------- device scratch ----------------
__device__ uint32_t d_kf[HEADS * NB * HBLK];  // K B-frag fp16 (k=dim, n=token)
__device__ uint32_t d_vf[HEADS * NB * HBLK];  // V B-frag fp16 (k=token, n=dim)
__device__ float d_qp[HEADS * NB * HDIM];
__device__ float d_kp[HEADS * NB * HDIM];
__device__ unsigned long long d_maskbits[HEADS * NB];

// qkv2 position j -> original token index (verified round 1)
__device__ __forceinline__ int perm_of(int j) {
    if (j < 3840) {
        int b = j >> 7, w = j & 127;
        int fn = b / 6, hn = (b % 6) / 3, wn = b % 3;
        int f2 = w >> 6, r = (w >> 3) & 7, c = w & 7;
        return FFLN + (fn * 2 + f2) * 384 + (hn * 8 + r) * 24 + (wn * 8 + c);
    } else if (j < 4224) {
        return j - 3840;
    } else {
        return j;
    }
}

__device__ __forceinline__ uint32_t pack_hf2(float lo, float hi) {
    uint32_t r;
    asm("cvt.rn.f16x2.f32 %0, %1, %2;" : "=r"(r) : "f"(hi), "f"(lo));
    return r;
}
__device__ __forceinline__ float ex2f(float x) {
    float y;
    asm("ex2.approx.ftz.f32 %0, %1;" : "=f"(y) : "f"(x));
    return y;
}

// fp16 m16n8k16 B-frag builder: kx = MMA k-index, nx = MMA n-index;
// adjacent 8-wide n-tiles paired into one uint4 slot.
// returns fp16 element index (u32 slot * 2 + half)
__device__ __forceinline__ int idxBhf(int kx, int nx) {
    int kc = kx >> 4, kk = kx & 15;
    int q4 = (kk >> 1) & 3, hk = kk >> 3, half = kk & 1;
    int np = nx >> 4, odd = (nx >> 3) & 1, g = nx & 7;
    int slot = ((kc * 8 + np) * 32 + g * 4 + q4) * 4 + odd * 2 + hk;
    return slot * 2 + half;
}
// fp16 m16n8k16 A-frag (Q/P, 128 rows): r = row (0..127), c = k-index (0..127)
__device__ __forceinline__ int idxAhf(int r, int c) {
    int slot = (((c >> 4) * 8 + (r >> 4)) * 32 + (r & 7) * 4 + ((c >> 1) & 3)) * 4
             + ((r >> 3) & 1) + (((c >> 3) & 1) << 1);
    return slot * 2 + (c & 1);
}

__device__ __forceinline__ void mma_f16(float c[4], const uint32_t a[4], uint32_t b0, uint32_t b1) {
    asm volatile(
        "mma.sync.aligned.m16n8k16.row.col.f32.f16.f16.f32 "
        "{%0,%1,%2,%3}, {%4,%5,%6,%7}, {%8,%9}, {%0,%1,%2,%3};\n"
        : "+f"(c[0]), "+f"(c[1]), "+f"(c[2]), "+f"(c[3])
        : "r"(a[0]), "r"(a[1]), "r"(a[2]), "r"(a[3]), "r"(b0), "r"(b1));
}

__device__ __forceinline__ void cp16(uint32_t s, const void* g) {
    asm volatile("cp.async.cg.shared.global [%0], [%1], 16;" :: "r"(s), "l"(g));
}
#define CP_COMMIT() asm volatile("cp.async.commit_group;")
#define CP_WAIT0()  asm volatile("cp.async.wait_group 0;")

// ---------------- 1) gather/permute K,V + pool q,k ------------------------
// grid (NB, HEADS, 3), 512 threads: z=0 q-pool, z=1 K frags + pool, z=2 V frags.
__global__ void gather_k(const float* __restrict__ q,
                         const float* __restrict__ k,
                         const float* __restrict__ v) {
    extern __shared__ uint32_t stg[];            // HBLK u32
    float* psm = (float*)(stg + HBLK);           // 512
    int* sperm = (int*)(psm + 512);              // 128
    const int bl = blockIdx.x, h = blockIdx.y, z = blockIdx.z;
    const int tid = threadIdx.x;
    const int d = tid & 127, t0 = tid >> 7;      // t0 in 0..3

    if (tid < 128)
        sperm[tid] = perm_of(bl * POOL + tid) * (HEADS * HDIM) + h * HDIM;
    __syncthreads();

    if (z == 0) {
        float part = 0.f;
#pragma unroll 16
        for (int i = 0; i < 32; i++) part += q[(size_t)sperm[t0 + 4 * i] + d];
        psm[tid] = part;
        __syncthreads();
        if (tid < 128)
            d_qp[(size_t)(h * NB + bl) * HDIM + tid] =
                (psm[tid] + psm[tid + 128] + psm[tid + 256] + psm[tid + 384])
                * (1.0f / POOL);
    } else if (z == 1) {
        __half* hstg = (__half*)stg;
        float part = 0.f;
#pragma unroll 16
        for (int i = 0; i < 32; i++) {
            int t = t0 + 4 * i;
            float val = k[(size_t)sperm[t] + d];
            part += val;
            hstg[idxBhf(d, t)] = __float2half(val);   // k-index = dim, n = token
        }
        psm[tid] = part;
        __syncthreads();
        uint4* dst = (uint4*)(d_kf + (size_t)(h * NB + bl) * HBLK);
        const uint4* src = (const uint4*)stg;
#pragma unroll
        for (int i = 0; i < 4; i++) dst[tid + 512 * i] = src[tid + 512 * i];
        if (tid < 128)
            d_kp[(size_t)(h * NB + bl) * HDIM + tid] =
                (psm[tid] + psm[tid + 128] + psm[tid + 256] + psm[tid + 384])
                * (1.0f / POOL);
    } else {
        __half* hstg = (__half*)stg;
#pragma unroll 16
        for (int i = 0; i < 32; i++) {
            int t = t0 + 4 * i;
            hstg[idxBhf(t, d)] = __float2half(v[(size_t)sperm[t] + d]);  // k = token, n = dim
        }
        __syncthreads();
        uint4* dst = (uint4*)(d_vf + (size_t)(h * NB + bl) * HBLK);
        const uint4* src = (const uint4*)stg;
#pragma unroll
        for (int i = 0; i < 4; i++) dst[tid + 512 * i] = src[tid + 512 * i];
    }
}

// ---------------- 2) top-4 threshold -> block mask ------------------------
__global__ void mask_k() {
    int l = blockIdx.x, h = blockIdx.y;
    __shared__ float lg[NB];
    int s = threadIdx.x;
    if (s < NB) {
        const float* qv = d_qp + ((size_t)h * NB + l) * HDIM;
        const float* kv = d_kp + ((size_t)h * NB + s) * HDIM;
        float acc = 0.f;
        for (int t = 0; t < HDIM; t++) acc += qv[t] * kv[t];
        lg[s] = acc;
    }
    __syncthreads();
    if (threadIdx.x == 0) {
        float vals[NB];
        for (int i = 0; i < NB; i++) vals[i] = lg[i];
        float thr = 0.f;
        for (int it = 0; it < KEEP; it++) {
            int bi = 0; float bv = -INFINITY;
            for (int i = 0; i < NB; i++) if (vals[i] > bv) { bv = vals[i]; bi = i; }
            thr = bv; vals[bi] = -INFINITY;
        }
        unsigned long long m = 0;
        for (int i = 0; i < NB; i++) if (lg[i] >= thr) m |= 1ull << i;
        m |= ((1ull << PROT) - 1ull) << (NB - PROT);
        if (l >= NB - PROT) m = (1ull << NB) - 1ull;
        d_maskbits[(size_t)h * NB + l] = m;
    }
}

// ---------------- 3) single-barrier pipelined fp16 attention --------------
// One CTA per (qblock, head); 512 threads, 4x4 warp grid, warp tile 32x32.
// Deferred-PV pipeline: iter i runs S_i, then PV_{i-1} interleaved with
// softmax_i (independent streams -> MUFU hidden under PV's LDS/HMMA).
// K, V, P all double-buffered; ONE __syncthreads per iteration.
__global__ void __launch_bounds__(512, 1)
attn_k(const float* __restrict__ qsrc, float* __restrict__ out) {
    extern __shared__ uint32_t sm[];
    uint32_t* sQ = sm;                          // 8192  (32KB)
    uint32_t* sKbuf = sm + 8192;                // 2 x 8192 (64KB)
    uint32_t* sVbuf = sm + 24576;               // 2 x 8192 (64KB)
    uint32_t* sPbuf = sm + 40960;               // 2 x 8192 (64KB)
    float* lsm = (float*)(sm + 57344);          // 128 x 4
    int* sperm = (int*)(lsm + 512);             // 128

    // heavy-first ordering: qb 30..35 first
    int bx = blockIdx.x;
    int qb, h;
    if (bx < 48) { qb = 30 + (bx >> 3); h = bx & 7; }
    else         { int t = bx - 48; qb = t >> 3; h = t & 7; }

    const int tid = threadIdx.x;
    const int lane = tid & 31, wid = tid >> 5;
    const int wn = wid & 3, wm = wid >> 2;      // 4 x 4 warp grid
    const int g = lane >> 2, q4 = lane & 3;

    uint32_t sbase = (uint32_t)__cvta_generic_to_shared(sm);
    uint32_t sKa = sbase + 8192 * 4, sVa = sbase + 24576 * 4, sPa = sbase + 40960 * 4;

    unsigned long long mb = d_maskbits[(size_t)h * NB + qb];
    int kb = __ffsll((long long)mb) - 1;        // block for S_i / V_i
    mb &= mb - 1;
    int kb_next = mb ? (__ffsll((long long)mb) - 1) : -1;

    if (tid < 128)
        sperm[tid] = perm_of(qb * POOL + tid) * (HEADS * HDIM) + h * HDIM;

    // prologue group: K_0 -> Kbuf0
    {
        const uint32_t* gk = d_kf + (size_t)(h * NB + kb) * HBLK;
#pragma unroll
        for (int i = 0; i < 4; i++) { int u = tid + 512 * i; cp16(sKa + u * 16, gk + u * 4); }
        CP_COMMIT();
    }

    // gather Q (128 x 128 -> fp16 A-frags), overlapping cp.async arrival
    __syncthreads();  // sperm ready
    {
        const float scale = 0.12751743f;        // 128^-0.5 * log2(e)
        const int dq = tid & 127, r0 = tid >> 7;
        __half* hQ = (__half*)sQ;
#pragma unroll 8
        for (int i = 0; i < 32; i++) {
            int r = r0 + 4 * i;
            hQ[idxAhf(r, dq)] = __float2half(qsrc[(size_t)sperm[r] + dq] * scale);
        }
    }

    float o[2][4][4];
#pragma unroll
    for (int m = 0; m < 2; m++)
#pragma unroll
        for (int n = 0; n < 4; n++)
#pragma unroll
            for (int r = 0; r < 4; r++) o[m][n][r] = 0.f;
    float lr[2][2] = {{0.f, 0.f}, {0.f, 0.f}};

    int first = 1, cur = 0;     // cur = i & 1
    for (;;) {
        CP_WAIT0();             // {K_i, V_{i-1}} arrived
        __syncthreads();        // arrivals + P_{i-1} STS visible; prev iter's
                                // smem reads complete -> alt buffers free

        // issue {K_{i+1} -> Kbuf[cur^1], V_i -> Vbuf[cur]} as one group
        if (kb_next >= 0) {
            const uint32_t* gk2 = d_kf + (size_t)(h * NB + kb_next) * HBLK;
            uint32_t ka = sKa + (uint32_t)(cur ^ 1) * 32768;
#pragma unroll
            for (int i = 0; i < 4; i++) { int u = tid + 512 * i; cp16(ka + u * 16, gk2 + u * 4); }
        }
        {
            const uint32_t* gv = d_vf + (size_t)(h * NB + kb) * HBLK;
            uint32_t va = sVa + (uint32_t)cur * 32768;
#pragma unroll
            for (int i = 0; i < 4; i++) { int u = tid + 512 * i; cp16(va + u * 16, gv + u * 4); }
        }
        CP_COMMIT();

        const uint32_t* sK = sKbuf + cur * 8192;

        // ---- S_i = Q K^T (warp tile 32 x 32) ----
        float sacc[2][4][4];
#pragma unroll
        for (int m = 0; m < 2; m++)
#pragma unroll
            for (int n = 0; n < 4; n++)
#pragma unroll
                for (int r = 0; r < 4; r++) sacc[m][n][r] = 0.f;
#pragma unroll 4
        for (int kt = 0; kt < 8; kt++) {
            uint32_t a[2][4];
#pragma unroll
            for (int m = 0; m < 2; m++)
                *(uint4*)a[m] = *(const uint4*)(sQ + ((kt * 8 + wm * 2 + m) * 32 + lane) * 4);
#pragma unroll
            for (int j = 0; j < 2; j++) {
                uint4 b = *(const uint4*)(sK + ((kt * 8 + wn * 2 + j) * 32 + lane) * 4);
#pragma unroll
                for (int m = 0; m < 2; m++) {
                    mma_f16(sacc[m][2 * j],     a[m], b.x, b.y);
                    mma_f16(sacc[m][2 * j + 1], a[m], b.z, b.w);
                }
            }
        }

        // ---- PV_{i-1} (reads sP/sV buffer cur^1) -- independent of sacc;
        //      ptxas interleaves the softmax MUFU below with this GEMM ----
        if (!first) {
            const uint32_t* sPp = sPbuf + (cur ^ 1) * 8192;
            const uint32_t* sVp = sVbuf + (cur ^ 1) * 8192;
#pragma unroll 4
            for (int kt = 0; kt < 8; kt++) {
                uint32_t a[2][4];
#pragma unroll
                for (int m = 0; m < 2; m++)
                    *(uint4*)a[m] = *(const uint4*)(sPp + ((kt * 8 + wm * 2 + m) * 32 + lane) * 4);
#pragma unroll
                for (int j = 0; j < 2; j++) {
                    uint4 b = *(const uint4*)(sVp + ((kt * 8 + wn * 2 + j) * 32 + lane) * 4);
#pragma unroll
                    for (int m = 0; m < 2; m++) {
                        mma_f16(o[m][2 * j],     a[m], b.x, b.y);
                        mma_f16(o[m][2 * j + 1], a[m], b.z, b.w);
                    }
                }
            }
        }

        // ---- softmax_i (no max; S pre-scaled by log2e) -> P_i STS ----
        {
            uint32_t* sPc = sPbuf + cur * 8192;
#pragma unroll
            for (int m = 0; m < 2; m++)
#pragma unroll
                for (int j = 0; j < 2; j++) {
                    float e0 = ex2f(sacc[m][2 * j][0]);
                    float e1 = ex2f(sacc[m][2 * j][1]);
                    float e2 = ex2f(sacc[m][2 * j][2]);
                    float e3 = ex2f(sacc[m][2 * j][3]);
                    float f0 = ex2f(sacc[m][2 * j + 1][0]);
                    float f1 = ex2f(sacc[m][2 * j + 1][1]);
                    float f2 = ex2f(sacc[m][2 * j + 1][2]);
                    float f3 = ex2f(sacc[m][2 * j + 1][3]);
                    lr[m][0] += e0 + e1 + f0 + f1;
                    lr[m][1] += e2 + e3 + f2 + f3;
                    uint4 w4;
                    w4.x = pack_hf2(e0, e1);
                    w4.y = pack_hf2(e2, e3);
                    w4.z = pack_hf2(f0, f1);
                    w4.w = pack_hf2(f2, f3);
                    int kc = wn * 2 + j;
                    *(uint4*)(sPc + ((kc * 8 + wm * 2 + m) * 32 + lane) * 4) = w4;
                }
        }

        first = 0;
        if (kb_next < 0) break;
        kb = kb_next;
        mb &= mb - 1;
        kb_next = mb ? (__ffsll((long long)mb) - 1) : -1;
        cur ^= 1;
    }

    // ---- tail: final PV_{n-1} ----
    CP_WAIT0();             // V_{n-1} arrived
    __syncthreads();        // + P_{n-1} visible
    {
        const uint32_t* sPp = sPbuf + cur * 8192;
        const uint32_t* sVp = sVbuf + cur * 8192;
#pragma unroll 4
        for (int kt = 0; kt < 8; kt++) {
            uint32_t a[2][4];
#pragma unroll
            for (int m = 0; m < 2; m++)
                *(uint4*)a[m] = *(const uint4*)(sPp + ((kt * 8 + wm * 2 + m) * 32 + lane) * 4);
#pragma unroll
            for (int j = 0; j < 2; j++) {
                uint4 b = *(const uint4*)(sVp + ((kt * 8 + wn * 2 + j) * 32 + lane) * 4);
#pragma unroll
                for (int m = 0; m < 2; m++) {
                    mma_f16(o[m][2 * j],     a[m], b.x, b.y);
                    mma_f16(o[m][2 * j + 1], a[m], b.z, b.w);
                }
            }
        }
    }

    // ---- epilogue: reduce l across 4 wn warps, normalize, permuted store ----
#pragma unroll
    for (int m = 0; m < 2; m++)
#pragma unroll
        for (int hh = 0; hh < 2; hh++) {
            float s = lr[m][hh];
            s += __shfl_xor_sync(0xffffffffu, s, 1);
            s += __shfl_xor_sync(0xffffffffu, s, 2);
            if (q4 == 0)
                lsm[(wm * 32 + m * 16 + hh * 8 + g) * 4 + wn] = s;
        }
    __syncthreads();
#pragma unroll
    for (int m = 0; m < 2; m++)
#pragma unroll
        for (int hh = 0; hh < 2; hh++) {
            int r = wm * 32 + m * 16 + hh * 8 + g;
            float inv = 1.0f / (lsm[r * 4] + lsm[r * 4 + 1] + lsm[r * 4 + 2] + lsm[r * 4 + 3]);
            float* og = out + sperm[r];
#pragma unroll
            for (int n = 0; n < 4; n++) {
                int c = wn * 32 + n * 8 + 2 * q4;
                *(float2*)(og + c) = make_float2(o[m][n][hh * 2] * inv,
                                                 o[m][n][hh * 2 + 1] * inv);
            }
        }
}

// ---------------- launch ----------------
extern "C" void kernel_launch(void* const* d_in, const int* in_sizes, int n_in,
                              void* d_out, int out_size) {
    const float* q = (const float*)d_in[0];
    const float* k = (const float*)d_in[1];
    const float* v = (const float*)d_in[2];
    float* out = (float*)d_out;

    const int gsmem = HBLK * 4 + 512 * 4 + 128 * 4;
    cudaFuncSetAttribute(gather_k, cudaFuncAttributeMaxDynamicSharedMemorySize, gsmem);

    const int asmem = (57344 + 512 + 128) * 4;   // 231936 B -> 1 CTA/SM
    cudaFuncSetAttribute(attn_k, cudaFuncAttributeMaxDynamicSharedMemorySize, asmem);

    gather_k<<<dim3(NB, HEADS, 3), 512, gsmem>>>(q, k, v);
    mask_k<<<dim3(NB, HEADS), 64>>>();
    attn_k<<<NB * HEADS, 512, asmem>>>(q, out);
}